// round 10
// baseline (speedup 1.0000x reference)
#include <cuda_runtime.h>
#include <math.h>

// Fixed problem shapes
#define Bv   16
#define Cc   256
#define Nn   64
#define NN   4096
#define Ss   128
#define EPSN 1e-12f
#define SCALE 10.0f
#define TPB  512     // 8 teams x 64 threads

typedef unsigned long long ull;

// Scratch: normalized sentence features + offsets
__device__ float g_sn1[Ss * Cc];
__device__ float g_sn2[Ss * Cc];
__device__ int   g_off[Bv + 1];

// Packed dual-fp32 FMA / ADD (Blackwell)
#define FFMA2(acc, a, bb) \
    asm("fma.rn.f32x2 %0, %1, %2, %0;" : "+l"(acc) : "l"(a), "l"(bb))
#define FADD2(dst, a, bb) \
    asm("add.rn.f32x2 %0, %1, %2;" : "=l"(dst) : "l"(a), "l"(bb))

// cp.async: 16-byte global->shared (L2-only), per-warp group pipeline
#define CP_ASYNC16(dst_u32, src_ptr) \
    asm volatile("cp.async.cg.shared.global [%0], [%1], 16;" \
                 :: "r"(dst_u32), "l"(src_ptr) : "memory")
#define CP_COMMIT() \
    asm volatile("cp.async.commit_group;" ::: "memory")
#define CP_WAIT3() \
    asm volatile("cp.async.wait_group 3;" ::: "memory")
#define CP_WAIT0() \
    asm volatile("cp.async.wait_group 0;" ::: "memory")

__device__ __forceinline__ float f2lo(ull x) {
    return __uint_as_float((unsigned)(x & 0xffffffffu));
}
__device__ __forceinline__ float f2hi(ull x) {
    return __uint_as_float((unsigned)(x >> 32));
}
__device__ __forceinline__ ull dup32(unsigned x) {
    ull d;
    asm("mov.b64 %0, {%1, %1};" : "=l"(d) : "r"(x));
    return d;
}
__device__ __forceinline__ unsigned smem_u32(const void* p) {
    return (unsigned)__cvta_generic_to_shared(p);
}

// ---------------------------------------------------------------------------
// Kernel 1: normalize sentence features (warp per row) + prefix offsets
// ---------------------------------------------------------------------------
__global__ void prep_kernel(const float* __restrict__ sf1,
                            const float* __restrict__ sf2,
                            const int*   __restrict__ nums) {
    if (blockIdx.x == 0 && threadIdx.x == 0) {
        int acc = 0;
        g_off[0] = 0;
        #pragma unroll
        for (int i = 0; i < Bv; i++) { acc += nums[i]; g_off[i + 1] = acc; }
    }
    int warp = threadIdx.x >> 5;
    int lane = threadIdx.x & 31;
    int row  = blockIdx.x * 8 + warp;   // 2S rows
    const float* src;
    float* dst;
    if (row < Ss) { src = sf1 + (size_t)row * Cc;        dst = g_sn1 + (size_t)row * Cc; }
    else          { src = sf2 + (size_t)(row - Ss) * Cc; dst = g_sn2 + (size_t)(row - Ss) * Cc; }

    float v[8];
    float sum = 0.f;
    #pragma unroll
    for (int k = 0; k < 8; k++) {
        v[k] = src[lane + 32 * k];
        sum += v[k] * v[k];
    }
    #pragma unroll
    for (int o = 16; o; o >>= 1) sum += __shfl_xor_sync(0xffffffffu, sum, o);
    float inv = 1.f / fmaxf(sqrtf(sum), EPSN);
    #pragma unroll
    for (int k = 0; k < 8; k++) dst[lane + 32 * k] = v[k] * inv;
}

// ---------------------------------------------------------------------------
// Kernel 2: fused dual-space scoring, cp.async.cg 16B streaming.
// Block = 512 thr = 8 teams x 64. team = (space sp, channel-quarter q).
// Thread owns 4 adjacent columns (16 B). Video streamed via per-warp 4-slot
// cp.async.cg ring (512 B/warp-op: max bytes per in-flight load slot, zero
// register cost). FFMA2 lanes = sentence pairs (unduplicated sentence smem,
// 2 broadcast LDS.128/channel). Partials reduced via a 3-level smem tree;
// team (0,0) runs the fused epilogue. grid = (16,16), block 512.
// Static smem = 16K sent + 32K ring = 48 KB (ring+sent alias as scratch).
// ---------------------------------------------------------------------------
__global__ __launch_bounds__(TPB, 2) void score_kernel(
    const float* __restrict__ vf1,
    const float* __restrict__ vf2,
    const float* __restrict__ mask2d,
    float* __restrict__ out) {

    // sentence pairs: idx sp*1024 + c*4 + p  (2048 ull, 16 KB);
    // post-loop: norm scratch, slot S -> (S*64+ttid)*2
    __shared__ __align__(16) ull sent[2048];
    // video ring: warp w -> ring + w*256 ull; slot j -> +j*64; lane -> +lane*2
    // post-loop: acc scratch, slot S -> (S*64+ttid)*16  (4 slots x 1024 ull)
    __shared__ __align__(16) ull ring[4096];

    const int tid  = threadIdx.x;
    const int team = tid >> 6;       // 0..7
    const int ttid = tid & 63;
    const int sp   = team >> 2;      // feature space
    const int q    = team & 3;       // channel quarter
    const int w    = tid >> 5;       // warp 0..15
    const int lane = tid & 31;
    const int b    = blockIdx.y;
    const int ij0  = blockIdx.x * 256 + 4 * ttid;

    const int start = g_off[b];
    int end = g_off[b + 1];
    if (end > Ss) end = Ss;
    if (start >= end) return;        // uniform per block

    const float* vf = (sp == 0) ? vf1 : vf2;
    const float* __restrict__ vbase =
        vf + ((size_t)b * Cc + (size_t)q * 64) * NN + ij0;

    const unsigned rw_u32 = smem_u32(ring) + (unsigned)w * 2048u +
                            (unsigned)lane * 16u;
    const ull* __restrict__ rr = ring + (size_t)w * 256 + (size_t)lane * 2;
    const ull* __restrict__ sbp = sent + (size_t)sp * 1024 + (size_t)q * 256;

    for (int cs = start; cs < end; cs += 8) {
        const int cnt = min(8, end - cs);

        // Stage sentence pairs {s2p, s2p+1}: 2048 ull, all 512 threads
        for (int e = tid; e < 2048; e += TPB) {
            const int p   = e & 3;
            const int c   = (e >> 2) & (Cc - 1);
            const int spp = e >> 10;
            const float* g = spp ? g_sn2 : g_sn1;
            float x0 = 0.f, x1 = 0.f;
            if (2 * p < cnt)     x0 = g[(size_t)(cs + 2 * p) * Cc + c];
            if (2 * p + 1 < cnt) x1 = g[(size_t)(cs + 2 * p + 1) * Cc + c];
            float2 d = make_float2(x0, x1);
            sent[e] = *reinterpret_cast<ull*>(&d);
        }
        __syncthreads();

        // acc[c*4+p]: lanes = (sent 2p, sent 2p+1), c = column 0..3
        ull acc[16];
        #pragma unroll
        for (int i = 0; i < 16; i++) acc[i] = 0ull;
        ull nrm01 = 0ull, nrm23 = 0ull;   // lanes = (col0,col1)/(col2,col3)

        // Preload channels 0..3 into the 4-slot ring
        #pragma unroll
        for (int j = 0; j < 4; j++) {
            CP_ASYNC16(rw_u32 + (unsigned)j * 512u,
                       vbase + (size_t)j * NN);
            CP_COMMIT();
        }

        #pragma unroll 4
        for (int k = 0; k < 60; k++) {
            CP_WAIT3();                 // slot k&3 (group k) complete
            const ulonglong2 av = *reinterpret_cast<const ulonglong2*>(
                rr + (size_t)(k & 3) * 64);
            // refill slot with channel k+4
            CP_ASYNC16(rw_u32 + (unsigned)((k + 4) & 3) * 512u,
                       vbase + (size_t)(k + 4) * NN);
            CP_COMMIT();

            FFMA2(nrm01, av.x, av.x);
            FFMA2(nrm23, av.y, av.y);
            const ull d0 = dup32((unsigned)av.x);
            const ull d1 = dup32((unsigned)(av.x >> 32));
            const ull d2 = dup32((unsigned)av.y);
            const ull d3 = dup32((unsigned)(av.y >> 32));
            const ulonglong2* p2 =
                reinterpret_cast<const ulonglong2*>(sbp + k * 4);
            const ulonglong2 q0 = p2[0];   // {s0,s1},{s2,s3}
            const ulonglong2 q1 = p2[1];   // {s4,s5},{s6,s7}
            FFMA2(acc[0],  d0, q0.x); FFMA2(acc[1],  d0, q0.y);
            FFMA2(acc[2],  d0, q1.x); FFMA2(acc[3],  d0, q1.y);
            FFMA2(acc[4],  d1, q0.x); FFMA2(acc[5],  d1, q0.y);
            FFMA2(acc[6],  d1, q1.x); FFMA2(acc[7],  d1, q1.y);
            FFMA2(acc[8],  d2, q0.x); FFMA2(acc[9],  d2, q0.y);
            FFMA2(acc[10], d2, q1.x); FFMA2(acc[11], d2, q1.y);
            FFMA2(acc[12], d3, q0.x); FFMA2(acc[13], d3, q0.y);
            FFMA2(acc[14], d3, q1.x); FFMA2(acc[15], d3, q1.y);
        }
        CP_WAIT0();                     // channels 60..63 all landed
        #pragma unroll
        for (int k = 60; k < 64; k++) {
            const ulonglong2 av = *reinterpret_cast<const ulonglong2*>(
                rr + (size_t)(k & 3) * 64);
            FFMA2(nrm01, av.x, av.x);
            FFMA2(nrm23, av.y, av.y);
            const ull d0 = dup32((unsigned)av.x);
            const ull d1 = dup32((unsigned)(av.x >> 32));
            const ull d2 = dup32((unsigned)av.y);
            const ull d3 = dup32((unsigned)(av.y >> 32));
            const ulonglong2* p2 =
                reinterpret_cast<const ulonglong2*>(sbp + k * 4);
            const ulonglong2 q0 = p2[0];
            const ulonglong2 q1 = p2[1];
            FFMA2(acc[0],  d0, q0.x); FFMA2(acc[1],  d0, q0.y);
            FFMA2(acc[2],  d0, q1.x); FFMA2(acc[3],  d0, q1.y);
            FFMA2(acc[4],  d1, q0.x); FFMA2(acc[5],  d1, q0.y);
            FFMA2(acc[6],  d1, q1.x); FFMA2(acc[7],  d1, q1.y);
            FFMA2(acc[8],  d2, q0.x); FFMA2(acc[9],  d2, q0.y);
            FFMA2(acc[10], d2, q1.x); FFMA2(acc[11], d2, q1.y);
            FFMA2(acc[12], d3, q0.x); FFMA2(acc[13], d3, q0.y);
            FFMA2(acc[14], d3, q1.x); FFMA2(acc[15], d3, q1.y);
        }
        __syncthreads();   // ring/sent reads done -> reduction scratch

        // Scratch helpers: slot S -> acc at ring[(S*64+ttid)*16],
        //                  norms at sent[(S*64+ttid)*2]
        #define PUB(S) do {                                              \
            ull* ra = ring + ((size_t)(S) * 64 + ttid) * 16;             \
            _Pragma("unroll")                                            \
            for (int i = 0; i < 16; i++) ra[i] = acc[i];                 \
            ull* rn = sent + ((size_t)(S) * 64 + ttid) * 2;              \
            rn[0] = nrm01; rn[1] = nrm23;                                \
        } while (0)
        #define ADDIN(S) do {                                            \
            const ull* ra = ring + ((size_t)(S) * 64 + ttid) * 16;       \
            _Pragma("unroll")                                            \
            for (int i = 0; i < 16; i++) FADD2(acc[i], acc[i], ra[i]);   \
            const ull* rn = sent + ((size_t)(S) * 64 + ttid) * 2;        \
            FADD2(nrm01, nrm01, rn[0]);                                  \
            FADD2(nrm23, nrm23, rn[1]);                                  \
        } while (0)

        // L1: quarters 1,3 publish; quarters 0,2 add
        if (q == 1) PUB(sp * 2);
        if (q == 3) PUB(sp * 2 + 1);
        __syncthreads();
        if (q == 0) ADDIN(sp * 2);
        if (q == 2) ADDIN(sp * 2 + 1);
        __syncthreads();
        // L2: quarter 2 publishes; quarter 0 adds
        if (q == 2) PUB(sp);
        __syncthreads();
        if (q == 0) ADDIN(sp);
        __syncthreads();
        // L3: space-1 q0 publishes to slot 0; team (0,0) consumes
        if (q == 0 && sp == 1) PUB(0);
        __syncthreads();

        if (team == 0) {
            const ull* ra2 = ring + ((size_t)0 * 64 + ttid) * 16;
            const ull* rn2 = sent + ((size_t)0 * 64 + ttid) * 2;
            const ull n2a = rn2[0], n2b = rn2[1];

            const float i1[4] = {
                1.f / fmaxf(sqrtf(f2lo(nrm01)), EPSN),
                1.f / fmaxf(sqrtf(f2hi(nrm01)), EPSN),
                1.f / fmaxf(sqrtf(f2lo(nrm23)), EPSN),
                1.f / fmaxf(sqrtf(f2hi(nrm23)), EPSN)
            };
            const float i2[4] = {
                1.f / fmaxf(sqrtf(f2lo(n2a)), EPSN),
                1.f / fmaxf(sqrtf(f2hi(n2a)), EPSN),
                1.f / fmaxf(sqrtf(f2lo(n2b)), EPSN),
                1.f / fmaxf(sqrtf(f2hi(n2b)), EPSN)
            };
            const float4 mv = *reinterpret_cast<const float4*>(mask2d + ij0);
            const float m[4] = { mv.x, mv.y, mv.z, mv.w };

            for (int s = 0; s < cnt; s++) {
                const size_t srow = (size_t)(cs + s);
                const int p = s >> 1;
                const bool hi = (s & 1) != 0;
                float lg[4], sc[4];
                #pragma unroll
                for (int c = 0; c < 4; c++) {
                    const ull t1 = acc[c * 4 + p];
                    const ull t2 = ra2[c * 4 + p];
                    const float d1 = hi ? f2hi(t1) : f2lo(t1);
                    const float d2 = hi ? f2hi(t2) : f2lo(t2);
                    lg[c] = SCALE * (d1 * i1[c]);
                    const float iou = m[c] / (1.f + __expf(-lg[c]));
                    const float con =
                        fmaxf((d2 * i2[c] + 1.f) * 0.5f * m[c], 0.f);
                    sc[c] = sqrtf(con) * iou;
                }
                *reinterpret_cast<float4*>(out + srow * NN + ij0) =
                    make_float4(lg[0], lg[1], lg[2], lg[3]);
                *reinterpret_cast<float4*>(
                    out + (size_t)Ss * NN + srow * NN + ij0) =
                    make_float4(sc[0], sc[1], sc[2], sc[3]);
            }
        }
        __syncthreads();   // scratch safe to restage
        #undef PUB
        #undef ADDIN
    }
}

// ---------------------------------------------------------------------------
extern "C" void kernel_launch(void* const* d_in, const int* in_sizes, int n_in,
                              void* d_out, int out_size) {
    const float* vf1  = (const float*)d_in[0];
    const float* vf2  = (const float*)d_in[1];
    const float* sf1  = (const float*)d_in[2];
    const float* sf2  = (const float*)d_in[3];
    const float* mask = (const float*)d_in[4];
    const int*   nums = (const int*)d_in[5];
    float* out = (float*)d_out;

    prep_kernel<<<(2 * Ss) / 8, 256>>>(sf1, sf2, nums);
    score_kernel<<<dim3(NN / 256, Bv), TPB>>>(vf1, vf2, mask, out);
}